// round 6
// baseline (speedup 1.0000x reference)
#include <cuda_runtime.h>
#include <cstdint>

#define D128 128
#define VT   64
#define MCTA 128
#define THR  512
#define EPSF 1e-8f

__device__ float g_x2[16384];
__device__ float g_c2[8192];

// smem float offsets
#define XF   0              // 128 x 132 fp32 X tile
#define CH   16896          // 64 x 132 tf32-hi C tile
#define CL   25344          // 64 x 132 tf32-lo C tile
#define WB   33792          // 64 x 136 k-major W buffer
#define C2S  42496          // 64 codeword norms
#define SMEM_FLOATS 42560   // 170,240 bytes
// end-of-kernel reuse: RS_* over CH/CL region, inv over WB region
#define RS_SUM  CH
#define RS_MIND (CH + 2048)
#define RS_MINI (CH + 4096)
#define RINV    WB

static __device__ __forceinline__ uint32_t tf32_rna(float x) {
    uint32_t r; asm("cvt.rna.tf32.f32 %0, %1;" : "=r"(r) : "f"(x)); return r;
}
static __device__ __forceinline__ uint32_t fbits(float x) { return __float_as_uint(x); }

static __device__ __forceinline__ void mma8(float* d, const uint32_t* a,
                                            uint32_t b0, uint32_t b1) {
    asm volatile("mma.sync.aligned.m16n8k8.row.col.f32.tf32.tf32.f32 "
        "{%0,%1,%2,%3}, {%4,%5,%6,%7}, {%8,%9}, {%0,%1,%2,%3};"
        : "+f"(d[0]), "+f"(d[1]), "+f"(d[2]), "+f"(d[3])
        : "r"(a[0]), "r"(a[1]), "r"(a[2]), "r"(a[3]), "r"(b0), "r"(b1));
}

// -------- norms pre-kernel (one warp per row) --------
__global__ void norms_kernel(const float* __restrict__ x,
                             const float* __restrict__ cb, int n, int v) {
    int gw   = (blockIdx.x * blockDim.x + threadIdx.x) >> 5;
    int lane = threadIdx.x & 31;
    if (gw >= n + v) return;
    const float* src = (gw < n) ? (x + (size_t)gw * D128) : (cb + (size_t)(gw - n) * D128);
    float4 val = ((const float4*)src)[lane];
    float s = val.x*val.x + val.y*val.y + val.z*val.z + val.w*val.w;
    #pragma unroll
    for (int off = 16; off; off >>= 1) s += __shfl_xor_sync(0xffffffffu, s, off);
    if (lane == 0) { if (gw < n) g_x2[gw] = s; else g_c2[gw - n] = s; }
}

// -------- fused SoftVQ, 16 warps: 32 rows/warp, V- and N- quarter splits --------
__global__ void __launch_bounds__(THR, 1) softvq_mma(
    const float* __restrict__ x, const float* __restrict__ cb,
    float* __restrict__ out_embed, float* __restrict__ out_idx, int n, int v)
{
    extern __shared__ float sm[];
    const int t   = threadIdx.x;
    const int w   = t >> 5;
    const int l   = t & 31;
    const int r0l = l >> 2;          // row within m16 block (0..7)
    const int cql = l & 3;           // quad column id
    const int g   = w >> 2;          // row-group (0..3): rows g*32 .. g*32+31
    const int q   = w & 3;           // quarter split id (0..3)
    const int m0  = blockIdx.x * MCTA;

    // ---- load X tile [128x128] fp32 into smem (stride 132) ----
    #pragma unroll
    for (int i = 0; i < 8; i++) {
        int f   = i * THR + t;
        int row = f >> 5;
        int c4  = (f & 31) * 4;
        float4 xv = *(const float4*)(x + (size_t)(m0 + row) * D128 + c4);
        *(float4*)(sm + XF + row * 132 + c4) = xv;
    }

    float x2r[2][2];
    #pragma unroll
    for (int mb = 0; mb < 2; mb++) {
        x2r[mb][0] = g_x2[m0 + g * 32 + mb * 16 + r0l];
        x2r[mb][1] = g_x2[m0 + g * 32 + mb * 16 + r0l + 8];
    }

    float e[2][4][4];
    #pragma unroll
    for (int mb = 0; mb < 2; mb++)
        #pragma unroll
        for (int i = 0; i < 4; i++)
            #pragma unroll
            for (int j = 0; j < 4; j++) e[mb][i][j] = 0.0f;

    float wsum[2][2] = {{0.f,0.f},{0.f,0.f}};
    float mind[2][2] = {{3.4e38f,3.4e38f},{3.4e38f,3.4e38f}};
    int   mini[2][2] = {{1<<30,1<<30},{1<<30,1<<30}};

    const int NTILES = v / VT;   // 128

    for (int tile = 0; tile < NTILES; tile++) {
        __syncthreads();   // prev tile's GEMM2 reads of CH/CL/WB complete
        const int v0 = tile * VT;
        // ---- load C tile [64x128], split hi/lo (RNA) ----
        #pragma unroll
        for (int i = 0; i < 4; i++) {
            int f   = i * THR + t;
            int row = f >> 5;
            int c4  = (f & 31) * 4;
            float4 cv = *(const float4*)(cb + (size_t)(v0 + row) * D128 + c4);
            float h0 = __uint_as_float(tf32_rna(cv.x));
            float h1 = __uint_as_float(tf32_rna(cv.y));
            float h2 = __uint_as_float(tf32_rna(cv.z));
            float h3 = __uint_as_float(tf32_rna(cv.w));
            float l0 = __uint_as_float(tf32_rna(cv.x - h0));
            float l1 = __uint_as_float(tf32_rna(cv.y - h1));
            float l2 = __uint_as_float(tf32_rna(cv.z - h2));
            float l3 = __uint_as_float(tf32_rna(cv.w - h3));
            int base = row * 132 + c4;
            *(float4*)(sm + CH + base) = make_float4(h0, h1, h2, h3);
            *(float4*)(sm + CL + base) = make_float4(l0, l1, l2, l3);
        }
        if (t < VT) sm[C2S + t] = g_c2[v0 + t];
        __syncthreads();

        // ---- GEMM1: S[32 x 16] per warp, 3 tf32 products, on-the-fly A split ----
        float s[2][2][4];
        #pragma unroll
        for (int mb = 0; mb < 2; mb++)
            #pragma unroll
            for (int i = 0; i < 2; i++)
                #pragma unroll
                for (int j = 0; j < 4; j++) s[mb][i][j] = 0.0f;

        #pragma unroll 2
        for (int kt = 0; kt < 16; kt++) {
            const int k0 = kt * 8 + cql;
            uint32_t ah[2][4], al[2][4];
            #pragma unroll
            for (int mb = 0; mb < 2; mb++) {
                int rb = (g * 32 + mb * 16 + r0l) * 132;
                float xv0 = sm[XF + rb + k0];
                float xv1 = sm[XF + rb + 8 * 132 + k0];
                float xv2 = sm[XF + rb + k0 + 4];
                float xv3 = sm[XF + rb + 8 * 132 + k0 + 4];
                ah[mb][0] = tf32_rna(xv0);
                ah[mb][1] = tf32_rna(xv1);
                ah[mb][2] = tf32_rna(xv2);
                ah[mb][3] = tf32_rna(xv3);
                al[mb][0] = tf32_rna(xv0 - __uint_as_float(ah[mb][0]));
                al[mb][1] = tf32_rna(xv1 - __uint_as_float(ah[mb][1]));
                al[mb][2] = tf32_rna(xv2 - __uint_as_float(ah[mb][2]));
                al[mb][3] = tf32_rna(xv3 - __uint_as_float(ah[mb][3]));
            }
            #pragma unroll
            for (int nt = 0; nt < 2; nt++) {
                int br = (q * 16 + nt * 8 + r0l) * 132 + k0;
                uint32_t bh0 = fbits(sm[CH + br]);
                uint32_t bh1 = fbits(sm[CH + br + 4]);
                uint32_t bl0 = fbits(sm[CL + br]);
                uint32_t bl1 = fbits(sm[CL + br + 4]);
                #pragma unroll
                for (int mb = 0; mb < 2; mb++) {
                    mma8(s[mb][nt], ah[mb], bh0, bh1);
                    mma8(s[mb][nt], al[mb], bh0, bh1);
                    mma8(s[mb][nt], ah[mb], bl0, bl1);
                }
            }
        }

        // ---- epilogue: d, min/sum, W -> tf32 into k-major smem buffer ----
        #pragma unroll
        for (int mb = 0; mb < 2; mb++) {
            #pragma unroll
            for (int nt = 0; nt < 2; nt++) {
                const float* sv = s[mb][nt];
                int cwb  = q * 16 + nt * 8 + 2 * cql;
                float c2a = sm[C2S + cwb];
                float c2b = sm[C2S + cwb + 1];
                int ib = v0 + cwb;

                float d00 = sqrtf(fmaxf(fmaf(-2.0f, sv[0], x2r[mb][0] + c2a), 0.0f));
                float d01 = sqrtf(fmaxf(fmaf(-2.0f, sv[1], x2r[mb][0] + c2b), 0.0f));
                float d10 = sqrtf(fmaxf(fmaf(-2.0f, sv[2], x2r[mb][1] + c2a), 0.0f));
                float d11 = sqrtf(fmaxf(fmaf(-2.0f, sv[3], x2r[mb][1] + c2b), 0.0f));

                if (d00 < mind[mb][0]) { mind[mb][0] = d00; mini[mb][0] = ib; }
                if (d01 < mind[mb][0]) { mind[mb][0] = d01; mini[mb][0] = ib + 1; }
                if (d10 < mind[mb][1]) { mind[mb][1] = d10; mini[mb][1] = ib; }
                if (d11 < mind[mb][1]) { mind[mb][1] = d11; mini[mb][1] = ib + 1; }

                float w00 = d00 + EPSF, w01 = d01 + EPSF;
                float w10 = d10 + EPSF, w11 = d11 + EPSF;
                wsum[mb][0] += w00 + w01;
                wsum[mb][1] += w10 + w11;

                int row = g * 32 + mb * 16 + r0l;
                sm[WB + cwb * 136 + row]           = __uint_as_float(tf32_rna(w00));
                sm[WB + (cwb + 1) * 136 + row]     = __uint_as_float(tf32_rna(w01));
                sm[WB + cwb * 136 + row + 8]       = __uint_as_float(tf32_rna(w10));
                sm[WB + (cwb + 1) * 136 + row + 8] = __uint_as_float(tf32_rna(w11));
            }
        }
        __syncthreads();   // WB complete for all warps

        // ---- GEMM2: E[32 x 32] += W[32 x 64] * C[64 x cols q*32..] ----
        #pragma unroll 2
        for (int kt2 = 0; kt2 < 8; kt2++) {
            const int kk = kt2 * 8 + cql;
            uint32_t a[2][4];
            #pragma unroll
            for (int mb = 0; mb < 2; mb++) {
                int row = g * 32 + mb * 16 + r0l;
                a[mb][0] = fbits(sm[WB + kk * 136 + row]);
                a[mb][1] = fbits(sm[WB + kk * 136 + row + 8]);
                a[mb][2] = fbits(sm[WB + (kk + 4) * 136 + row]);
                a[mb][3] = fbits(sm[WB + (kk + 4) * 136 + row + 8]);
            }
            #pragma unroll
            for (int nt2 = 0; nt2 < 4; nt2++) {
                int col = q * 32 + nt2 * 8 + r0l;
                uint32_t b0 = fbits(sm[CH + kk * 132 + col]);
                uint32_t b1 = fbits(sm[CH + (kk + 4) * 132 + col]);
                mma8(e[0][nt2], a[0], b0, b1);
                mma8(e[1][nt2], a[1], b0, b1);
            }
        }
    }

    // ---- final reduction: combine per-warp partials across the 4 q-splits ----
    __syncthreads();   // last GEMM2 reads of CH/WB done; safe to reuse
    #pragma unroll
    for (int mb = 0; mb < 2; mb++)
        #pragma unroll
        for (int r = 0; r < 2; r++) {
            int row = g * 32 + mb * 16 + r0l + r * 8;
            int bi  = row * 16 + q * 4 + cql;
            sm[RS_SUM  + bi] = wsum[mb][r];
            sm[RS_MIND + bi] = mind[mb][r];
            ((int*)sm)[RS_MINI + bi] = mini[mb][r];
        }
    __syncthreads();
    if (t < MCTA) {
        float ssum = 0.0f, bd = 3.4e38f;
        int bi = 1 << 30;
        #pragma unroll
        for (int j = 0; j < 16; j++) {
            ssum += sm[RS_SUM + t * 16 + j];
            float dj = sm[RS_MIND + t * 16 + j];
            int   ij = ((int*)sm)[RS_MINI + t * 16 + j];
            if (dj < bd || (dj == bd && ij < bi)) { bd = dj; bi = ij; }
        }
        sm[RINV + t] = 1.0f / ssum;
        if (out_idx != nullptr) out_idx[m0 + t] = (float)bi;
    }
    __syncthreads();

    // ---- embed output: each warp writes its 32 rows x 32 cols ----
    #pragma unroll
    for (int mb = 0; mb < 2; mb++) {
        int row0 = g * 32 + mb * 16 + r0l;
        float inv0 = sm[RINV + row0];
        float inv1 = sm[RINV + row0 + 8];
        #pragma unroll
        for (int nt2 = 0; nt2 < 4; nt2++) {
            int col = q * 32 + nt2 * 8 + 2 * cql;
            float2 o0 = make_float2(e[mb][nt2][0] * inv0, e[mb][nt2][1] * inv0);
            float2 o1 = make_float2(e[mb][nt2][2] * inv1, e[mb][nt2][3] * inv1);
            *(float2*)(out_embed + (size_t)(m0 + row0) * D128 + col)     = o0;
            *(float2*)(out_embed + (size_t)(m0 + row0 + 8) * D128 + col) = o1;
        }
    }
}

extern "C" void kernel_launch(void* const* d_in, const int* in_sizes, int n_in,
                              void* d_out, int out_size) {
    const float* x  = (const float*)d_in[0];
    const float* cb = (const float*)d_in[1];
    int n = in_sizes[0] / D128;   // 16384
    int v = in_sizes[1] / D128;   // 8192
    float* out  = (float*)d_out;
    float* oidx = ((long long)out_size >= (long long)n * D128 + n)
                      ? out + (size_t)n * D128 : nullptr;

    int nblocks = ((n + v) * 32 + 255) / 256;
    norms_kernel<<<nblocks, 256>>>(x, cb, n, v);

    cudaFuncSetAttribute(softvq_mma, cudaFuncAttributeMaxDynamicSharedMemorySize,
                         SMEM_FLOATS * sizeof(float));
    softvq_mma<<<n / MCTA, THR, SMEM_FLOATS * sizeof(float)>>>(x, cb, out, oidx, n, v);
}

// round 7
// speedup vs baseline: 1.0006x; 1.0006x over previous
#include <cuda_runtime.h>
#include <cstdint>

#define D128 128
#define VT   64
#define MCTA 128
#define THR  512
#define EPSF 1e-8f

__device__ float g_x2[16384];
__device__ float g_c2[8192];

// smem float offsets
#define XF   0              // 128 x 132 fp32 X tile
#define CH   16896          // 64 x 132 tf32-hi C tile
#define CL   25344          // 64 x 132 tf32-lo C tile
#define WB   33792          // 64 x 136 k-major W buffer
#define C2S  42496          // 64 codeword norms
#define SMEM_FLOATS 42560   // 170,240 bytes
// end-of-kernel reuse: RS_* over CH/CL region, inv over WB region
#define RS_SUM  CH
#define RS_MIND (CH + 2048)
#define RS_MINI (CH + 4096)
#define RINV    WB

static __device__ __forceinline__ uint32_t tf32_rna(float x) {
    uint32_t r; asm("cvt.rna.tf32.f32 %0, %1;" : "=r"(r) : "f"(x)); return r;
}
static __device__ __forceinline__ uint32_t fbits(float x) { return __float_as_uint(x); }

static __device__ __forceinline__ void mma8(float* d, const uint32_t* a,
                                            uint32_t b0, uint32_t b1) {
    asm volatile("mma.sync.aligned.m16n8k8.row.col.f32.tf32.tf32.f32 "
        "{%0,%1,%2,%3}, {%4,%5,%6,%7}, {%8,%9}, {%0,%1,%2,%3};"
        : "+f"(d[0]), "+f"(d[1]), "+f"(d[2]), "+f"(d[3])
        : "r"(a[0]), "r"(a[1]), "r"(a[2]), "r"(a[3]), "r"(b0), "r"(b1));
}

// -------- norms pre-kernel (one warp per row) --------
__global__ void norms_kernel(const float* __restrict__ x,
                             const float* __restrict__ cb, int n, int v) {
    int gw   = (blockIdx.x * blockDim.x + threadIdx.x) >> 5;
    int lane = threadIdx.x & 31;
    if (gw >= n + v) return;
    const float* src = (gw < n) ? (x + (size_t)gw * D128) : (cb + (size_t)(gw - n) * D128);
    float4 val = ((const float4*)src)[lane];
    float s = val.x*val.x + val.y*val.y + val.z*val.z + val.w*val.w;
    #pragma unroll
    for (int off = 16; off; off >>= 1) s += __shfl_xor_sync(0xffffffffu, s, off);
    if (lane == 0) { if (gw < n) g_x2[gw] = s; else g_c2[gw - n] = s; }
}

// -------- fused SoftVQ, 16 warps: 32 rows/warp, V- and N- quarter splits --------
__global__ void __launch_bounds__(THR, 1) softvq_mma(
    const float* __restrict__ x, const float* __restrict__ cb,
    float* __restrict__ out_embed, float* __restrict__ out_idx, int n, int v)
{
    extern __shared__ float sm[];
    const int t   = threadIdx.x;
    const int w   = t >> 5;
    const int l   = t & 31;
    const int r0l = l >> 2;          // row within m16 block (0..7)
    const int cql = l & 3;           // quad column id
    const int g   = w >> 2;          // row-group (0..3): rows g*32 .. g*32+31
    const int q   = w & 3;           // quarter split id (0..3)
    const int m0  = blockIdx.x * MCTA;

    // ---- load X tile [128x128] fp32 into smem (stride 132) ----
    #pragma unroll
    for (int i = 0; i < 8; i++) {
        int f   = i * THR + t;
        int row = f >> 5;
        int c4  = (f & 31) * 4;
        float4 xv = *(const float4*)(x + (size_t)(m0 + row) * D128 + c4);
        *(float4*)(sm + XF + row * 132 + c4) = xv;
    }

    float x2r[2][2];
    #pragma unroll
    for (int mb = 0; mb < 2; mb++) {
        x2r[mb][0] = g_x2[m0 + g * 32 + mb * 16 + r0l];
        x2r[mb][1] = g_x2[m0 + g * 32 + mb * 16 + r0l + 8];
    }

    float e[2][4][4];
    #pragma unroll
    for (int mb = 0; mb < 2; mb++)
        #pragma unroll
        for (int i = 0; i < 4; i++)
            #pragma unroll
            for (int j = 0; j < 4; j++) e[mb][i][j] = 0.0f;

    float wsum[2][2] = {{0.f,0.f},{0.f,0.f}};
    float mind[2][2] = {{3.4e38f,3.4e38f},{3.4e38f,3.4e38f}};
    int   mini[2][2] = {{1<<30,1<<30},{1<<30,1<<30}};

    const int NTILES = v / VT;   // 128

    for (int tile = 0; tile < NTILES; tile++) {
        __syncthreads();   // prev tile's GEMM2 reads of CH/CL/WB complete
        const int v0 = tile * VT;
        // ---- load C tile [64x128], split hi/lo (RNA) ----
        #pragma unroll
        for (int i = 0; i < 4; i++) {
            int f   = i * THR + t;
            int row = f >> 5;
            int c4  = (f & 31) * 4;
            float4 cv = *(const float4*)(cb + (size_t)(v0 + row) * D128 + c4);
            float h0 = __uint_as_float(tf32_rna(cv.x));
            float h1 = __uint_as_float(tf32_rna(cv.y));
            float h2 = __uint_as_float(tf32_rna(cv.z));
            float h3 = __uint_as_float(tf32_rna(cv.w));
            float l0 = __uint_as_float(tf32_rna(cv.x - h0));
            float l1 = __uint_as_float(tf32_rna(cv.y - h1));
            float l2 = __uint_as_float(tf32_rna(cv.z - h2));
            float l3 = __uint_as_float(tf32_rna(cv.w - h3));
            int base = row * 132 + c4;
            *(float4*)(sm + CH + base) = make_float4(h0, h1, h2, h3);
            *(float4*)(sm + CL + base) = make_float4(l0, l1, l2, l3);
        }
        if (t < VT) sm[C2S + t] = g_c2[v0 + t];
        __syncthreads();

        // ---- GEMM1: S[32 x 16] per warp, 3 tf32 products, on-the-fly A split ----
        float s[2][2][4];
        #pragma unroll
        for (int mb = 0; mb < 2; mb++)
            #pragma unroll
            for (int i = 0; i < 2; i++)
                #pragma unroll
                for (int j = 0; j < 4; j++) s[mb][i][j] = 0.0f;

        #pragma unroll 2
        for (int kt = 0; kt < 16; kt++) {
            const int k0 = kt * 8 + cql;
            uint32_t ah[2][4], al[2][4];
            #pragma unroll
            for (int mb = 0; mb < 2; mb++) {
                int rb = (g * 32 + mb * 16 + r0l) * 132;
                float xv0 = sm[XF + rb + k0];
                float xv1 = sm[XF + rb + 8 * 132 + k0];
                float xv2 = sm[XF + rb + k0 + 4];
                float xv3 = sm[XF + rb + 8 * 132 + k0 + 4];
                ah[mb][0] = tf32_rna(xv0);
                ah[mb][1] = tf32_rna(xv1);
                ah[mb][2] = tf32_rna(xv2);
                ah[mb][3] = tf32_rna(xv3);
                al[mb][0] = tf32_rna(xv0 - __uint_as_float(ah[mb][0]));
                al[mb][1] = tf32_rna(xv1 - __uint_as_float(ah[mb][1]));
                al[mb][2] = tf32_rna(xv2 - __uint_as_float(ah[mb][2]));
                al[mb][3] = tf32_rna(xv3 - __uint_as_float(ah[mb][3]));
            }
            #pragma unroll
            for (int nt = 0; nt < 2; nt++) {
                int br = (q * 16 + nt * 8 + r0l) * 132 + k0;
                uint32_t bh0 = fbits(sm[CH + br]);
                uint32_t bh1 = fbits(sm[CH + br + 4]);
                uint32_t bl0 = fbits(sm[CL + br]);
                uint32_t bl1 = fbits(sm[CL + br + 4]);
                #pragma unroll
                for (int mb = 0; mb < 2; mb++) {
                    mma8(s[mb][nt], ah[mb], bh0, bh1);
                    mma8(s[mb][nt], al[mb], bh0, bh1);
                    mma8(s[mb][nt], ah[mb], bl0, bl1);
                }
            }
        }

        // ---- epilogue: d, min/sum, W -> tf32 into k-major smem buffer ----
        #pragma unroll
        for (int mb = 0; mb < 2; mb++) {
            #pragma unroll
            for (int nt = 0; nt < 2; nt++) {
                const float* sv = s[mb][nt];
                int cwb  = q * 16 + nt * 8 + 2 * cql;
                float c2a = sm[C2S + cwb];
                float c2b = sm[C2S + cwb + 1];
                int ib = v0 + cwb;

                float d00 = sqrtf(fmaxf(fmaf(-2.0f, sv[0], x2r[mb][0] + c2a), 0.0f));
                float d01 = sqrtf(fmaxf(fmaf(-2.0f, sv[1], x2r[mb][0] + c2b), 0.0f));
                float d10 = sqrtf(fmaxf(fmaf(-2.0f, sv[2], x2r[mb][1] + c2a), 0.0f));
                float d11 = sqrtf(fmaxf(fmaf(-2.0f, sv[3], x2r[mb][1] + c2b), 0.0f));

                if (d00 < mind[mb][0]) { mind[mb][0] = d00; mini[mb][0] = ib; }
                if (d01 < mind[mb][0]) { mind[mb][0] = d01; mini[mb][0] = ib + 1; }
                if (d10 < mind[mb][1]) { mind[mb][1] = d10; mini[mb][1] = ib; }
                if (d11 < mind[mb][1]) { mind[mb][1] = d11; mini[mb][1] = ib + 1; }

                float w00 = d00 + EPSF, w01 = d01 + EPSF;
                float w10 = d10 + EPSF, w11 = d11 + EPSF;
                wsum[mb][0] += w00 + w01;
                wsum[mb][1] += w10 + w11;

                int row = g * 32 + mb * 16 + r0l;
                sm[WB + cwb * 136 + row]           = __uint_as_float(tf32_rna(w00));
                sm[WB + (cwb + 1) * 136 + row]     = __uint_as_float(tf32_rna(w01));
                sm[WB + cwb * 136 + row + 8]       = __uint_as_float(tf32_rna(w10));
                sm[WB + (cwb + 1) * 136 + row + 8] = __uint_as_float(tf32_rna(w11));
            }
        }
        __syncthreads();   // WB complete for all warps

        // ---- GEMM2: E[32 x 32] += W[32 x 64] * C[64 x cols q*32..] ----
        #pragma unroll 2
        for (int kt2 = 0; kt2 < 8; kt2++) {
            const int kk = kt2 * 8 + cql;
            uint32_t a[2][4];
            #pragma unroll
            for (int mb = 0; mb < 2; mb++) {
                int row = g * 32 + mb * 16 + r0l;
                a[mb][0] = fbits(sm[WB + kk * 136 + row]);
                a[mb][1] = fbits(sm[WB + kk * 136 + row + 8]);
                a[mb][2] = fbits(sm[WB + (kk + 4) * 136 + row]);
                a[mb][3] = fbits(sm[WB + (kk + 4) * 136 + row + 8]);
            }
            #pragma unroll
            for (int nt2 = 0; nt2 < 4; nt2++) {
                int col = q * 32 + nt2 * 8 + r0l;
                uint32_t b0 = fbits(sm[CH + kk * 132 + col]);
                uint32_t b1 = fbits(sm[CH + (kk + 4) * 132 + col]);
                mma8(e[0][nt2], a[0], b0, b1);
                mma8(e[1][nt2], a[1], b0, b1);
            }
        }
    }

    // ---- final reduction: combine per-warp partials across the 4 q-splits ----
    __syncthreads();   // last GEMM2 reads of CH/WB done; safe to reuse
    #pragma unroll
    for (int mb = 0; mb < 2; mb++)
        #pragma unroll
        for (int r = 0; r < 2; r++) {
            int row = g * 32 + mb * 16 + r0l + r * 8;
            int bi  = row * 16 + q * 4 + cql;
            sm[RS_SUM  + bi] = wsum[mb][r];
            sm[RS_MIND + bi] = mind[mb][r];
            ((int*)sm)[RS_MINI + bi] = mini[mb][r];
        }
    __syncthreads();
    if (t < MCTA) {
        float ssum = 0.0f, bd = 3.4e38f;
        int bi = 1 << 30;
        #pragma unroll
        for (int j = 0; j < 16; j++) {
            ssum += sm[RS_SUM + t * 16 + j];
            float dj = sm[RS_MIND + t * 16 + j];
            int   ij = ((int*)sm)[RS_MINI + t * 16 + j];
            if (dj < bd || (dj == bd && ij < bi)) { bd = dj; bi = ij; }
        }
        sm[RINV + t] = 1.0f / ssum;
        if (out_idx != nullptr) out_idx[m0 + t] = (float)bi;
    }
    __syncthreads();

    // ---- embed output: each warp writes its 32 rows x 32 cols ----
    #pragma unroll
    for (int mb = 0; mb < 2; mb++) {
        int row0 = g * 32 + mb * 16 + r0l;
        float inv0 = sm[RINV + row0];
        float inv1 = sm[RINV + row0 + 8];
        #pragma unroll
        for (int nt2 = 0; nt2 < 4; nt2++) {
            int col = q * 32 + nt2 * 8 + 2 * cql;
            float2 o0 = make_float2(e[mb][nt2][0] * inv0, e[mb][nt2][1] * inv0);
            float2 o1 = make_float2(e[mb][nt2][2] * inv1, e[mb][nt2][3] * inv1);
            *(float2*)(out_embed + (size_t)(m0 + row0) * D128 + col)     = o0;
            *(float2*)(out_embed + (size_t)(m0 + row0 + 8) * D128 + col) = o1;
        }
    }
}

extern "C" void kernel_launch(void* const* d_in, const int* in_sizes, int n_in,
                              void* d_out, int out_size) {
    const float* x  = (const float*)d_in[0];
    const float* cb = (const float*)d_in[1];
    int n = in_sizes[0] / D128;   // 16384
    int v = in_sizes[1] / D128;   // 8192
    float* out  = (float*)d_out;
    float* oidx = ((long long)out_size >= (long long)n * D128 + n)
                      ? out + (size_t)n * D128 : nullptr;

    int nblocks = ((n + v) * 32 + 255) / 256;
    norms_kernel<<<nblocks, 256>>>(x, cb, n, v);

    cudaFuncSetAttribute(softvq_mma, cudaFuncAttributeMaxDynamicSharedMemorySize,
                         SMEM_FLOATS * sizeof(float));
    softvq_mma<<<n / MCTA, THR, SMEM_FLOATS * sizeof(float)>>>(x, cb, out, oidx, n, v);
}

// round 8
// speedup vs baseline: 1.0014x; 1.0008x over previous
#include <cuda_runtime.h>
#include <cstdint>

#define D128 128
#define VT   64
#define MCTA 128
#define THR  512
#define EPSF 1e-8f

__device__ float g_x2[16384];
__device__ float g_c2[8192];

// smem float offsets
#define XF   0              // 128 x 132 fp32 X tile
#define CH   16896          // 64 x 132 tf32-hi C tile
#define CL   25344          // 64 x 132 tf32-lo C tile
#define WB   33792          // 64 x 136 k-major W buffer
#define C2S  42496          // 64 codeword norms
#define SMEM_FLOATS 42560   // 170,240 bytes
// end-of-kernel reuse: RS_* over CH/CL region, inv over WB region
#define RS_SUM  CH
#define RS_MIND (CH + 2048)
#define RS_MINI (CH + 4096)
#define RINV    WB

static __device__ __forceinline__ uint32_t tf32_rna(float x) {
    uint32_t r; asm("cvt.rna.tf32.f32 %0, %1;" : "=r"(r) : "f"(x)); return r;
}
static __device__ __forceinline__ uint32_t fbits(float x) { return __float_as_uint(x); }

static __device__ __forceinline__ void mma8(float* d, const uint32_t* a,
                                            uint32_t b0, uint32_t b1) {
    asm volatile("mma.sync.aligned.m16n8k8.row.col.f32.tf32.tf32.f32 "
        "{%0,%1,%2,%3}, {%4,%5,%6,%7}, {%8,%9}, {%0,%1,%2,%3};"
        : "+f"(d[0]), "+f"(d[1]), "+f"(d[2]), "+f"(d[3])
        : "r"(a[0]), "r"(a[1]), "r"(a[2]), "r"(a[3]), "r"(b0), "r"(b1));
}

// -------- norms pre-kernel (one warp per row) --------
__global__ void norms_kernel(const float* __restrict__ x,
                             const float* __restrict__ cb, int n, int v) {
    int gw   = (blockIdx.x * blockDim.x + threadIdx.x) >> 5;
    int lane = threadIdx.x & 31;
    if (gw >= n + v) return;
    const float* src = (gw < n) ? (x + (size_t)gw * D128) : (cb + (size_t)(gw - n) * D128);
    float4 val = ((const float4*)src)[lane];
    float s = val.x*val.x + val.y*val.y + val.z*val.z + val.w*val.w;
    #pragma unroll
    for (int off = 16; off; off >>= 1) s += __shfl_xor_sync(0xffffffffu, s, off);
    if (lane == 0) { if (gw < n) g_x2[gw] = s; else g_c2[gw - n] = s; }
}

// -------- fused SoftVQ, 16 warps: 32 rows/warp, V- and N- quarter splits --------
__global__ void __launch_bounds__(THR, 1) softvq_mma(
    const float* __restrict__ x, const float* __restrict__ cb,
    float* __restrict__ out_embed, float* __restrict__ out_idx, int n, int v)
{
    extern __shared__ float sm[];
    const int t   = threadIdx.x;
    const int w   = t >> 5;
    const int l   = t & 31;
    const int r0l = l >> 2;          // row within m16 block (0..7)
    const int cql = l & 3;           // quad column id
    const int g   = w >> 2;          // row-group (0..3): rows g*32 .. g*32+31
    const int q   = w & 3;           // quarter split id (0..3)
    const int m0  = blockIdx.x * MCTA;

    // ---- load X tile [128x128] fp32 into smem (stride 132) ----
    #pragma unroll
    for (int i = 0; i < 8; i++) {
        int f   = i * THR + t;
        int row = f >> 5;
        int c4  = (f & 31) * 4;
        float4 xv = *(const float4*)(x + (size_t)(m0 + row) * D128 + c4);
        *(float4*)(sm + XF + row * 132 + c4) = xv;
    }

    float x2r[2][2];
    #pragma unroll
    for (int mb = 0; mb < 2; mb++) {
        x2r[mb][0] = g_x2[m0 + g * 32 + mb * 16 + r0l];
        x2r[mb][1] = g_x2[m0 + g * 32 + mb * 16 + r0l + 8];
    }

    float e[2][4][4];
    #pragma unroll
    for (int mb = 0; mb < 2; mb++)
        #pragma unroll
        for (int i = 0; i < 4; i++)
            #pragma unroll
            for (int j = 0; j < 4; j++) e[mb][i][j] = 0.0f;

    float wsum[2][2] = {{0.f,0.f},{0.f,0.f}};
    float mind[2][2] = {{3.4e38f,3.4e38f},{3.4e38f,3.4e38f}};
    int   mini[2][2] = {{1<<30,1<<30},{1<<30,1<<30}};

    const int NTILES = v / VT;   // 128

    for (int tile = 0; tile < NTILES; tile++) {
        __syncthreads();   // prev tile's GEMM2 reads of CH/CL/WB complete
        const int v0 = tile * VT;
        // ---- load C tile [64x128], split hi/lo (RNA) ----
        #pragma unroll
        for (int i = 0; i < 4; i++) {
            int f   = i * THR + t;
            int row = f >> 5;
            int c4  = (f & 31) * 4;
            float4 cv = *(const float4*)(cb + (size_t)(v0 + row) * D128 + c4);
            float h0 = __uint_as_float(tf32_rna(cv.x));
            float h1 = __uint_as_float(tf32_rna(cv.y));
            float h2 = __uint_as_float(tf32_rna(cv.z));
            float h3 = __uint_as_float(tf32_rna(cv.w));
            float l0 = __uint_as_float(tf32_rna(cv.x - h0));
            float l1 = __uint_as_float(tf32_rna(cv.y - h1));
            float l2 = __uint_as_float(tf32_rna(cv.z - h2));
            float l3 = __uint_as_float(tf32_rna(cv.w - h3));
            int base = row * 132 + c4;
            *(float4*)(sm + CH + base) = make_float4(h0, h1, h2, h3);
            *(float4*)(sm + CL + base) = make_float4(l0, l1, l2, l3);
        }
        if (t < VT) sm[C2S + t] = g_c2[v0 + t];
        __syncthreads();

        // ---- GEMM1: S[32 x 16] per warp, 3 tf32 products, on-the-fly A split ----
        float s[2][2][4];
        #pragma unroll
        for (int mb = 0; mb < 2; mb++)
            #pragma unroll
            for (int i = 0; i < 2; i++)
                #pragma unroll
                for (int j = 0; j < 4; j++) s[mb][i][j] = 0.0f;

        #pragma unroll 2
        for (int kt = 0; kt < 16; kt++) {
            const int k0 = kt * 8 + cql;
            uint32_t ah[2][4], al[2][4];
            #pragma unroll
            for (int mb = 0; mb < 2; mb++) {
                int rb = (g * 32 + mb * 16 + r0l) * 132;
                float xv0 = sm[XF + rb + k0];
                float xv1 = sm[XF + rb + 8 * 132 + k0];
                float xv2 = sm[XF + rb + k0 + 4];
                float xv3 = sm[XF + rb + 8 * 132 + k0 + 4];
                ah[mb][0] = tf32_rna(xv0);
                ah[mb][1] = tf32_rna(xv1);
                ah[mb][2] = tf32_rna(xv2);
                ah[mb][3] = tf32_rna(xv3);
                al[mb][0] = tf32_rna(xv0 - __uint_as_float(ah[mb][0]));
                al[mb][1] = tf32_rna(xv1 - __uint_as_float(ah[mb][1]));
                al[mb][2] = tf32_rna(xv2 - __uint_as_float(ah[mb][2]));
                al[mb][3] = tf32_rna(xv3 - __uint_as_float(ah[mb][3]));
            }
            #pragma unroll
            for (int nt = 0; nt < 2; nt++) {
                int br = (q * 16 + nt * 8 + r0l) * 132 + k0;
                uint32_t bh0 = fbits(sm[CH + br]);
                uint32_t bh1 = fbits(sm[CH + br + 4]);
                uint32_t bl0 = fbits(sm[CL + br]);
                uint32_t bl1 = fbits(sm[CL + br + 4]);
                #pragma unroll
                for (int mb = 0; mb < 2; mb++) {
                    mma8(s[mb][nt], ah[mb], bh0, bh1);
                    mma8(s[mb][nt], al[mb], bh0, bh1);
                    mma8(s[mb][nt], ah[mb], bl0, bl1);
                }
            }
        }

        // ---- epilogue: d, min/sum, W -> tf32 into k-major smem buffer ----
        #pragma unroll
        for (int mb = 0; mb < 2; mb++) {
            #pragma unroll
            for (int nt = 0; nt < 2; nt++) {
                const float* sv = s[mb][nt];
                int cwb  = q * 16 + nt * 8 + 2 * cql;
                float c2a = sm[C2S + cwb];
                float c2b = sm[C2S + cwb + 1];
                int ib = v0 + cwb;

                float d00 = sqrtf(fmaxf(fmaf(-2.0f, sv[0], x2r[mb][0] + c2a), 0.0f));
                float d01 = sqrtf(fmaxf(fmaf(-2.0f, sv[1], x2r[mb][0] + c2b), 0.0f));
                float d10 = sqrtf(fmaxf(fmaf(-2.0f, sv[2], x2r[mb][1] + c2a), 0.0f));
                float d11 = sqrtf(fmaxf(fmaf(-2.0f, sv[3], x2r[mb][1] + c2b), 0.0f));

                if (d00 < mind[mb][0]) { mind[mb][0] = d00; mini[mb][0] = ib; }
                if (d01 < mind[mb][0]) { mind[mb][0] = d01; mini[mb][0] = ib + 1; }
                if (d10 < mind[mb][1]) { mind[mb][1] = d10; mini[mb][1] = ib; }
                if (d11 < mind[mb][1]) { mind[mb][1] = d11; mini[mb][1] = ib + 1; }

                float w00 = d00 + EPSF, w01 = d01 + EPSF;
                float w10 = d10 + EPSF, w11 = d11 + EPSF;
                wsum[mb][0] += w00 + w01;
                wsum[mb][1] += w10 + w11;

                int row = g * 32 + mb * 16 + r0l;
                sm[WB + cwb * 136 + row]           = __uint_as_float(tf32_rna(w00));
                sm[WB + (cwb + 1) * 136 + row]     = __uint_as_float(tf32_rna(w01));
                sm[WB + cwb * 136 + row + 8]       = __uint_as_float(tf32_rna(w10));
                sm[WB + (cwb + 1) * 136 + row + 8] = __uint_as_float(tf32_rna(w11));
            }
        }
        __syncthreads();   // WB complete for all warps

        // ---- GEMM2: E[32 x 32] += W[32 x 64] * C[64 x cols q*32..] ----
        #pragma unroll 2
        for (int kt2 = 0; kt2 < 8; kt2++) {
            const int kk = kt2 * 8 + cql;
            uint32_t a[2][4];
            #pragma unroll
            for (int mb = 0; mb < 2; mb++) {
                int row = g * 32 + mb * 16 + r0l;
                a[mb][0] = fbits(sm[WB + kk * 136 + row]);
                a[mb][1] = fbits(sm[WB + kk * 136 + row + 8]);
                a[mb][2] = fbits(sm[WB + (kk + 4) * 136 + row]);
                a[mb][3] = fbits(sm[WB + (kk + 4) * 136 + row + 8]);
            }
            #pragma unroll
            for (int nt2 = 0; nt2 < 4; nt2++) {
                int col = q * 32 + nt2 * 8 + r0l;
                uint32_t b0 = fbits(sm[CH + kk * 132 + col]);
                uint32_t b1 = fbits(sm[CH + (kk + 4) * 132 + col]);
                mma8(e[0][nt2], a[0], b0, b1);
                mma8(e[1][nt2], a[1], b0, b1);
            }
        }
    }

    // ---- final reduction: combine per-warp partials across the 4 q-splits ----
    __syncthreads();   // last GEMM2 reads of CH/WB done; safe to reuse
    #pragma unroll
    for (int mb = 0; mb < 2; mb++)
        #pragma unroll
        for (int r = 0; r < 2; r++) {
            int row = g * 32 + mb * 16 + r0l + r * 8;
            int bi  = row * 16 + q * 4 + cql;
            sm[RS_SUM  + bi] = wsum[mb][r];
            sm[RS_MIND + bi] = mind[mb][r];
            ((int*)sm)[RS_MINI + bi] = mini[mb][r];
        }
    __syncthreads();
    if (t < MCTA) {
        float ssum = 0.0f, bd = 3.4e38f;
        int bi = 1 << 30;
        #pragma unroll
        for (int j = 0; j < 16; j++) {
            ssum += sm[RS_SUM + t * 16 + j];
            float dj = sm[RS_MIND + t * 16 + j];
            int   ij = ((int*)sm)[RS_MINI + t * 16 + j];
            if (dj < bd || (dj == bd && ij < bi)) { bd = dj; bi = ij; }
        }
        sm[RINV + t] = 1.0f / ssum;
        if (out_idx != nullptr) out_idx[m0 + t] = (float)bi;
    }
    __syncthreads();

    // ---- embed output: each warp writes its 32 rows x 32 cols ----
    #pragma unroll
    for (int mb = 0; mb < 2; mb++) {
        int row0 = g * 32 + mb * 16 + r0l;
        float inv0 = sm[RINV + row0];
        float inv1 = sm[RINV + row0 + 8];
        #pragma unroll
        for (int nt2 = 0; nt2 < 4; nt2++) {
            int col = q * 32 + nt2 * 8 + 2 * cql;
            float2 o0 = make_float2(e[mb][nt2][0] * inv0, e[mb][nt2][1] * inv0);
            float2 o1 = make_float2(e[mb][nt2][2] * inv1, e[mb][nt2][3] * inv1);
            *(float2*)(out_embed + (size_t)(m0 + row0) * D128 + col)     = o0;
            *(float2*)(out_embed + (size_t)(m0 + row0 + 8) * D128 + col) = o1;
        }
    }
}

extern "C" void kernel_launch(void* const* d_in, const int* in_sizes, int n_in,
                              void* d_out, int out_size) {
    const float* x  = (const float*)d_in[0];
    const float* cb = (const float*)d_in[1];
    int n = in_sizes[0] / D128;   // 16384
    int v = in_sizes[1] / D128;   // 8192
    float* out  = (float*)d_out;
    float* oidx = ((long long)out_size >= (long long)n * D128 + n)
                      ? out + (size_t)n * D128 : nullptr;

    int nblocks = ((n + v) * 32 + 255) / 256;
    norms_kernel<<<nblocks, 256>>>(x, cb, n, v);

    cudaFuncSetAttribute(softvq_mma, cudaFuncAttributeMaxDynamicSharedMemorySize,
                         SMEM_FLOATS * sizeof(float));
    softvq_mma<<<n / MCTA, THR, SMEM_FLOATS * sizeof(float)>>>(x, cb, out, oidx, n, v);
}

// round 9
// speedup vs baseline: 1.0024x; 1.0010x over previous
#include <cuda_runtime.h>
#include <cstdint>

#define D128 128
#define VT   64
#define MCTA 128
#define THR  512
#define EPSF 1e-8f

__device__ float g_x2[16384];
__device__ float g_c2[8192];

// smem float offsets
#define XF   0              // 128 x 132 fp32 X tile
#define CH   16896          // 64 x 132 tf32-hi C tile
#define CL   25344          // 64 x 132 tf32-lo C tile
#define WB   33792          // 64 x 136 k-major W buffer
#define C2S  42496          // 64 codeword norms
#define SMEM_FLOATS 42560   // 170,240 bytes
// end-of-kernel reuse: RS_* over CH/CL region, inv over WB region
#define RS_SUM  CH
#define RS_MIND (CH + 2048)
#define RS_MINI (CH + 4096)
#define RINV    WB

static __device__ __forceinline__ uint32_t tf32_rna(float x) {
    uint32_t r; asm("cvt.rna.tf32.f32 %0, %1;" : "=r"(r) : "f"(x)); return r;
}
static __device__ __forceinline__ uint32_t fbits(float x) { return __float_as_uint(x); }

static __device__ __forceinline__ void mma8(float* d, const uint32_t* a,
                                            uint32_t b0, uint32_t b1) {
    asm volatile("mma.sync.aligned.m16n8k8.row.col.f32.tf32.tf32.f32 "
        "{%0,%1,%2,%3}, {%4,%5,%6,%7}, {%8,%9}, {%0,%1,%2,%3};"
        : "+f"(d[0]), "+f"(d[1]), "+f"(d[2]), "+f"(d[3])
        : "r"(a[0]), "r"(a[1]), "r"(a[2]), "r"(a[3]), "r"(b0), "r"(b1));
}

// -------- norms pre-kernel (one warp per row) --------
__global__ void norms_kernel(const float* __restrict__ x,
                             const float* __restrict__ cb, int n, int v) {
    int gw   = (blockIdx.x * blockDim.x + threadIdx.x) >> 5;
    int lane = threadIdx.x & 31;
    if (gw >= n + v) return;
    const float* src = (gw < n) ? (x + (size_t)gw * D128) : (cb + (size_t)(gw - n) * D128);
    float4 val = ((const float4*)src)[lane];
    float s = val.x*val.x + val.y*val.y + val.z*val.z + val.w*val.w;
    #pragma unroll
    for (int off = 16; off; off >>= 1) s += __shfl_xor_sync(0xffffffffu, s, off);
    if (lane == 0) { if (gw < n) g_x2[gw] = s; else g_c2[gw - n] = s; }
}

// -------- fused SoftVQ, 16 warps: 32 rows/warp, V- and N- quarter splits --------
__global__ void __launch_bounds__(THR, 1) softvq_mma(
    const float* __restrict__ x, const float* __restrict__ cb,
    float* __restrict__ out_embed, float* __restrict__ out_idx, int n, int v)
{
    extern __shared__ float sm[];
    const int t   = threadIdx.x;
    const int w   = t >> 5;
    const int l   = t & 31;
    const int r0l = l >> 2;          // row within m16 block (0..7)
    const int cql = l & 3;           // quad column id
    const int g   = w >> 2;          // row-group (0..3): rows g*32 .. g*32+31
    const int q   = w & 3;           // quarter split id (0..3)
    const int m0  = blockIdx.x * MCTA;

    // ---- load X tile [128x128] fp32 into smem (stride 132) ----
    #pragma unroll
    for (int i = 0; i < 8; i++) {
        int f   = i * THR + t;
        int row = f >> 5;
        int c4  = (f & 31) * 4;
        float4 xv = *(const float4*)(x + (size_t)(m0 + row) * D128 + c4);
        *(float4*)(sm + XF + row * 132 + c4) = xv;
    }

    float x2r[2][2];
    #pragma unroll
    for (int mb = 0; mb < 2; mb++) {
        x2r[mb][0] = g_x2[m0 + g * 32 + mb * 16 + r0l];
        x2r[mb][1] = g_x2[m0 + g * 32 + mb * 16 + r0l + 8];
    }

    float e[2][4][4];
    #pragma unroll
    for (int mb = 0; mb < 2; mb++)
        #pragma unroll
        for (int i = 0; i < 4; i++)
            #pragma unroll
            for (int j = 0; j < 4; j++) e[mb][i][j] = 0.0f;

    float wsum[2][2] = {{0.f,0.f},{0.f,0.f}};
    float mind[2][2] = {{3.4e38f,3.4e38f},{3.4e38f,3.4e38f}};
    int   mini[2][2] = {{1<<30,1<<30},{1<<30,1<<30}};

    const int NTILES = v / VT;   // 128

    for (int tile = 0; tile < NTILES; tile++) {
        __syncthreads();   // prev tile's GEMM2 reads of CH/CL/WB complete
        const int v0 = tile * VT;
        // ---- load C tile [64x128], split hi/lo (RNA) ----
        #pragma unroll
        for (int i = 0; i < 4; i++) {
            int f   = i * THR + t;
            int row = f >> 5;
            int c4  = (f & 31) * 4;
            float4 cv = *(const float4*)(cb + (size_t)(v0 + row) * D128 + c4);
            float h0 = __uint_as_float(tf32_rna(cv.x));
            float h1 = __uint_as_float(tf32_rna(cv.y));
            float h2 = __uint_as_float(tf32_rna(cv.z));
            float h3 = __uint_as_float(tf32_rna(cv.w));
            float l0 = __uint_as_float(tf32_rna(cv.x - h0));
            float l1 = __uint_as_float(tf32_rna(cv.y - h1));
            float l2 = __uint_as_float(tf32_rna(cv.z - h2));
            float l3 = __uint_as_float(tf32_rna(cv.w - h3));
            int base = row * 132 + c4;
            *(float4*)(sm + CH + base) = make_float4(h0, h1, h2, h3);
            *(float4*)(sm + CL + base) = make_float4(l0, l1, l2, l3);
        }
        if (t < VT) sm[C2S + t] = g_c2[v0 + t];
        __syncthreads();

        // ---- GEMM1: S[32 x 16] per warp, 3 tf32 products, on-the-fly A split ----
        float s[2][2][4];
        #pragma unroll
        for (int mb = 0; mb < 2; mb++)
            #pragma unroll
            for (int i = 0; i < 2; i++)
                #pragma unroll
                for (int j = 0; j < 4; j++) s[mb][i][j] = 0.0f;

        #pragma unroll 2
        for (int kt = 0; kt < 16; kt++) {
            const int k0 = kt * 8 + cql;
            uint32_t ah[2][4], al[2][4];
            #pragma unroll
            for (int mb = 0; mb < 2; mb++) {
                int rb = (g * 32 + mb * 16 + r0l) * 132;
                float xv0 = sm[XF + rb + k0];
                float xv1 = sm[XF + rb + 8 * 132 + k0];
                float xv2 = sm[XF + rb + k0 + 4];
                float xv3 = sm[XF + rb + 8 * 132 + k0 + 4];
                ah[mb][0] = tf32_rna(xv0);
                ah[mb][1] = tf32_rna(xv1);
                ah[mb][2] = tf32_rna(xv2);
                ah[mb][3] = tf32_rna(xv3);
                al[mb][0] = tf32_rna(xv0 - __uint_as_float(ah[mb][0]));
                al[mb][1] = tf32_rna(xv1 - __uint_as_float(ah[mb][1]));
                al[mb][2] = tf32_rna(xv2 - __uint_as_float(ah[mb][2]));
                al[mb][3] = tf32_rna(xv3 - __uint_as_float(ah[mb][3]));
            }
            #pragma unroll
            for (int nt = 0; nt < 2; nt++) {
                int br = (q * 16 + nt * 8 + r0l) * 132 + k0;
                uint32_t bh0 = fbits(sm[CH + br]);
                uint32_t bh1 = fbits(sm[CH + br + 4]);
                uint32_t bl0 = fbits(sm[CL + br]);
                uint32_t bl1 = fbits(sm[CL + br + 4]);
                #pragma unroll
                for (int mb = 0; mb < 2; mb++) {
                    mma8(s[mb][nt], ah[mb], bh0, bh1);
                    mma8(s[mb][nt], al[mb], bh0, bh1);
                    mma8(s[mb][nt], ah[mb], bl0, bl1);
                }
            }
        }

        // ---- epilogue: d, min/sum, W -> tf32 into k-major smem buffer ----
        #pragma unroll
        for (int mb = 0; mb < 2; mb++) {
            #pragma unroll
            for (int nt = 0; nt < 2; nt++) {
                const float* sv = s[mb][nt];
                int cwb  = q * 16 + nt * 8 + 2 * cql;
                float c2a = sm[C2S + cwb];
                float c2b = sm[C2S + cwb + 1];
                int ib = v0 + cwb;

                float d00 = sqrtf(fmaxf(fmaf(-2.0f, sv[0], x2r[mb][0] + c2a), 0.0f));
                float d01 = sqrtf(fmaxf(fmaf(-2.0f, sv[1], x2r[mb][0] + c2b), 0.0f));
                float d10 = sqrtf(fmaxf(fmaf(-2.0f, sv[2], x2r[mb][1] + c2a), 0.0f));
                float d11 = sqrtf(fmaxf(fmaf(-2.0f, sv[3], x2r[mb][1] + c2b), 0.0f));

                if (d00 < mind[mb][0]) { mind[mb][0] = d00; mini[mb][0] = ib; }
                if (d01 < mind[mb][0]) { mind[mb][0] = d01; mini[mb][0] = ib + 1; }
                if (d10 < mind[mb][1]) { mind[mb][1] = d10; mini[mb][1] = ib; }
                if (d11 < mind[mb][1]) { mind[mb][1] = d11; mini[mb][1] = ib + 1; }

                float w00 = d00 + EPSF, w01 = d01 + EPSF;
                float w10 = d10 + EPSF, w11 = d11 + EPSF;
                wsum[mb][0] += w00 + w01;
                wsum[mb][1] += w10 + w11;

                int row = g * 32 + mb * 16 + r0l;
                sm[WB + cwb * 136 + row]           = __uint_as_float(tf32_rna(w00));
                sm[WB + (cwb + 1) * 136 + row]     = __uint_as_float(tf32_rna(w01));
                sm[WB + cwb * 136 + row + 8]       = __uint_as_float(tf32_rna(w10));
                sm[WB + (cwb + 1) * 136 + row + 8] = __uint_as_float(tf32_rna(w11));
            }
        }
        __syncthreads();   // WB complete for all warps

        // ---- GEMM2: E[32 x 32] += W[32 x 64] * C[64 x cols q*32..] ----
        #pragma unroll 2
        for (int kt2 = 0; kt2 < 8; kt2++) {
            const int kk = kt2 * 8 + cql;
            uint32_t a[2][4];
            #pragma unroll
            for (int mb = 0; mb < 2; mb++) {
                int row = g * 32 + mb * 16 + r0l;
                a[mb][0] = fbits(sm[WB + kk * 136 + row]);
                a[mb][1] = fbits(sm[WB + kk * 136 + row + 8]);
                a[mb][2] = fbits(sm[WB + (kk + 4) * 136 + row]);
                a[mb][3] = fbits(sm[WB + (kk + 4) * 136 + row + 8]);
            }
            #pragma unroll
            for (int nt2 = 0; nt2 < 4; nt2++) {
                int col = q * 32 + nt2 * 8 + r0l;
                uint32_t b0 = fbits(sm[CH + kk * 132 + col]);
                uint32_t b1 = fbits(sm[CH + (kk + 4) * 132 + col]);
                mma8(e[0][nt2], a[0], b0, b1);
                mma8(e[1][nt2], a[1], b0, b1);
            }
        }
    }

    // ---- final reduction: combine per-warp partials across the 4 q-splits ----
    __syncthreads();   // last GEMM2 reads of CH/WB done; safe to reuse
    #pragma unroll
    for (int mb = 0; mb < 2; mb++)
        #pragma unroll
        for (int r = 0; r < 2; r++) {
            int row = g * 32 + mb * 16 + r0l + r * 8;
            int bi  = row * 16 + q * 4 + cql;
            sm[RS_SUM  + bi] = wsum[mb][r];
            sm[RS_MIND + bi] = mind[mb][r];
            ((int*)sm)[RS_MINI + bi] = mini[mb][r];
        }
    __syncthreads();
    if (t < MCTA) {
        float ssum = 0.0f, bd = 3.4e38f;
        int bi = 1 << 30;
        #pragma unroll
        for (int j = 0; j < 16; j++) {
            ssum += sm[RS_SUM + t * 16 + j];
            float dj = sm[RS_MIND + t * 16 + j];
            int   ij = ((int*)sm)[RS_MINI + t * 16 + j];
            if (dj < bd || (dj == bd && ij < bi)) { bd = dj; bi = ij; }
        }
        sm[RINV + t] = 1.0f / ssum;
        if (out_idx != nullptr) out_idx[m0 + t] = (float)bi;
    }
    __syncthreads();

    // ---- embed output: each warp writes its 32 rows x 32 cols ----
    #pragma unroll
    for (int mb = 0; mb < 2; mb++) {
        int row0 = g * 32 + mb * 16 + r0l;
        float inv0 = sm[RINV + row0];
        float inv1 = sm[RINV + row0 + 8];
        #pragma unroll
        for (int nt2 = 0; nt2 < 4; nt2++) {
            int col = q * 32 + nt2 * 8 + 2 * cql;
            float2 o0 = make_float2(e[mb][nt2][0] * inv0, e[mb][nt2][1] * inv0);
            float2 o1 = make_float2(e[mb][nt2][2] * inv1, e[mb][nt2][3] * inv1);
            *(float2*)(out_embed + (size_t)(m0 + row0) * D128 + col)     = o0;
            *(float2*)(out_embed + (size_t)(m0 + row0 + 8) * D128 + col) = o1;
        }
    }
}

extern "C" void kernel_launch(void* const* d_in, const int* in_sizes, int n_in,
                              void* d_out, int out_size) {
    const float* x  = (const float*)d_in[0];
    const float* cb = (const float*)d_in[1];
    int n = in_sizes[0] / D128;   // 16384
    int v = in_sizes[1] / D128;   // 8192
    float* out  = (float*)d_out;
    float* oidx = ((long long)out_size >= (long long)n * D128 + n)
                      ? out + (size_t)n * D128 : nullptr;

    int nblocks = ((n + v) * 32 + 255) / 256;
    norms_kernel<<<nblocks, 256>>>(x, cb, n, v);

    cudaFuncSetAttribute(softvq_mma, cudaFuncAttributeMaxDynamicSharedMemorySize,
                         SMEM_FLOATS * sizeof(float));
    softvq_mma<<<n / MCTA, THR, SMEM_FLOATS * sizeof(float)>>>(x, cb, out, oidx, n, v);
}